// round 7
// baseline (speedup 1.0000x reference)
#include <cuda_runtime.h>
#include <cstdint>

// FFN_36867999269234 via mma.sync m16n8k16.f16 (f32 accum), zero-smem mainloop.
//   y = LN(x); h = relu(y·W1^T + b1); out = x + h·W2^T + b2
// Each lane (g=lane>>2, q=lane&3) OWNS x in the mma fragment layout:
//   x[g][2q..2q+1], x[g][2q+8..9], x[g+8][2q..], x[g+8][2q+8..]  (4x LDG.64)
// -> LN via two 4-lane butterflies, y==A1 fragment via cvt, C1 relu->A2 via
//    cvt (C-frag == A-frag slot identity), C2 layout == x layout -> register
//    residual + direct STG.64. No shared memory in the loop at all.

#define H 16
#define DM 64
#define LN_EPS 1e-5f

__device__ __forceinline__ uint32_t packh2(float lo, float hi) {
    uint32_t r;
    asm("cvt.rn.f16x2.f32 %0, %1, %2;" : "=r"(r) : "f"(hi), "f"(lo));
    return r;
}

__device__ __forceinline__ void mma_f16(float* c, const uint32_t* a, const uint32_t* b) {
    asm volatile(
        "mma.sync.aligned.m16n8k16.row.col.f32.f16.f16.f32 "
        "{%0,%1,%2,%3}, {%4,%5,%6,%7}, {%8,%9}, {%0,%1,%2,%3};"
        : "+f"(c[0]), "+f"(c[1]), "+f"(c[2]), "+f"(c[3])
        : "r"(a[0]), "r"(a[1]), "r"(a[2]), "r"(a[3]), "r"(b[0]), "r"(b[1]));
}

__global__ __launch_bounds__(128, 4) void ffn_mma(
    const float* __restrict__ x,
    const float* __restrict__ gamma,
    const float* __restrict__ beta,
    const float* __restrict__ w1,   // [DM, H]
    const float* __restrict__ b1,   // [DM]
    const float* __restrict__ w2,   // [H, DM]
    const float* __restrict__ b2,   // [H]
    float* __restrict__ out,
    int ntok)
{
    __shared__ float2 c1bs[8][4];   // folded b1, [ntile j][q] = cols 2q,2q+1
    __shared__ float2 c2bs[2][4];   // b2,        [ntile jn][q]

    const int tid  = threadIdx.x;
    const int wid  = tid >> 5;
    const int lane = tid & 31;
    const int g = lane >> 2;
    const int q = lane & 3;

    // ---------------- weight fragments (f16x2, registers) ----------------
    uint32_t B1[8][2];
    #pragma unroll
    for (int j = 0; j < 8; j++) {
        const float* wr = w1 + (8 * j + g) * H;
        B1[j][0] = packh2(wr[2 * q]     * gamma[2 * q],     wr[2 * q + 1] * gamma[2 * q + 1]);
        B1[j][1] = packh2(wr[2 * q + 8] * gamma[2 * q + 8], wr[2 * q + 9] * gamma[2 * q + 9]);
    }
    uint32_t B2[4][2][2];
    #pragma unroll
    for (int s = 0; s < 4; s++)
        #pragma unroll
        for (int jn = 0; jn < 2; jn++) {
            const float* wr = w2 + (8 * jn + g) * DM + 16 * s;
            B2[s][jn][0] = packh2(wr[2 * q],     wr[2 * q + 1]);
            B2[s][jn][1] = packh2(wr[2 * q + 8], wr[2 * q + 9]);
        }

    // ---------------- bias LUTs ----------------
    if (tid < 32) {
        int j = tid >> 2, qq = tid & 3;
        float a0 = b1[8 * j + 2 * qq], a1 = b1[8 * j + 2 * qq + 1];
        #pragma unroll
        for (int k = 0; k < H; k++) {
            a0 = fmaf(w1[(8 * j + 2 * qq) * H + k],     beta[k], a0);
            a1 = fmaf(w1[(8 * j + 2 * qq + 1) * H + k], beta[k], a1);
        }
        c1bs[j][qq] = make_float2(a0, a1);
    }
    if (tid < 8) {
        int jn = tid >> 2, qq = tid & 3;
        c2bs[jn][qq] = make_float2(b2[8 * jn + 2 * qq], b2[8 * jn + 2 * qq + 1]);
    }
    __syncthreads();

    // ---------------- token loop: 16 tokens per warp-tile -----------------
    const int ntiles = (ntok + 15) >> 4;   // ntok is a multiple of 16
    const int wstep  = gridDim.x * 4;
    int wt = blockIdx.x * 4 + wid;

    // prefetch first tile (fragment-layout loads)
    float2 xa, xb, xc, xd;
    {
        int tg = wt * 16 + g;
        if (tg + 8 >= ntok) tg = (ntok > 16) ? ntok - 16 : 0;
        const float2* p0 = (const float2*)(x + (long long)tg * H);
        const float2* p1 = (const float2*)(x + (long long)(tg + 8) * H);
        xa = p0[q]; xb = p0[q + 4];
        xc = p1[q]; xd = p1[q + 4];
    }

    for (; wt < ntiles; wt += wstep) {
        const int tg = wt * 16 + g;
        const float2 va = xa, vb = xb, vc = xc, vd = xd;

        // ---- LN: two row-sums via q-group butterflies ----
        float s0 = va.x + va.y + vb.x + vb.y;
        float s1 = vc.x + vc.y + vd.x + vd.y;
        float q0 = fmaf(va.x, va.x, va.y * va.y) + fmaf(vb.x, vb.x, vb.y * vb.y);
        float q1 = fmaf(vc.x, vc.x, vc.y * vc.y) + fmaf(vd.x, vd.x, vd.y * vd.y);
        s0 += __shfl_xor_sync(0xFFFFFFFFu, s0, 1);
        s1 += __shfl_xor_sync(0xFFFFFFFFu, s1, 1);
        q0 += __shfl_xor_sync(0xFFFFFFFFu, q0, 1);
        q1 += __shfl_xor_sync(0xFFFFFFFFu, q1, 1);
        s0 += __shfl_xor_sync(0xFFFFFFFFu, s0, 2);
        s1 += __shfl_xor_sync(0xFFFFFFFFu, s1, 2);
        q0 += __shfl_xor_sync(0xFFFFFFFFu, q0, 2);
        q1 += __shfl_xor_sync(0xFFFFFFFFu, q1, 2);
        const float m0 = s0 * (1.f / H);
        const float m1 = s1 * (1.f / H);
        const float r0 = rsqrtf(q0 * (1.f / H) - m0 * m0 + LN_EPS);
        const float r1 = rsqrtf(q1 * (1.f / H) - m1 * m1 + LN_EPS);

        // ---- y == A1 fragment, in-lane ----
        uint32_t A1[4];
        A1[0] = packh2((va.x - m0) * r0, (va.y - m0) * r0);
        A1[1] = packh2((vc.x - m1) * r1, (vc.y - m1) * r1);
        A1[2] = packh2((vb.x - m0) * r0, (vb.y - m0) * r0);
        A1[3] = packh2((vd.x - m1) * r1, (vd.y - m1) * r1);

        // ---- prefetch next tile ----
        {
            int nwt = wt + wstep;
            if (nwt < ntiles) {
                int tn = nwt * 16 + g;
                const float2* p0 = (const float2*)(x + (long long)tn * H);
                const float2* p1 = (const float2*)(x + (long long)(tn + 8) * H);
                xa = p0[q]; xb = p0[q + 4];
                xc = p1[q]; xd = p1[q + 4];
            }
        }

        // ---- MMA1: C1[16x64] = y·W1g^T + b1fold ----
        float C1[8][4];
        #pragma unroll
        for (int j = 0; j < 8; j++) {
            const float2 b = c1bs[j][q];
            C1[j][0] = b.x; C1[j][1] = b.y; C1[j][2] = b.x; C1[j][3] = b.y;
            mma_f16(C1[j], A1, B1[j]);
        }

        // ---- MMA2: C2[16x16] = relu(C1)·W2^T + b2 (C->A frag identity) ----
        float C2[2][4];
        #pragma unroll
        for (int jn = 0; jn < 2; jn++) {
            const float2 b = c2bs[jn][q];
            C2[jn][0] = b.x; C2[jn][1] = b.y; C2[jn][2] = b.x; C2[jn][3] = b.y;
        }
        #pragma unroll
        for (int s = 0; s < 4; s++) {
            uint32_t A2[4];
            A2[0] = packh2(fmaxf(C1[2 * s][0], 0.f),     fmaxf(C1[2 * s][1], 0.f));
            A2[1] = packh2(fmaxf(C1[2 * s][2], 0.f),     fmaxf(C1[2 * s][3], 0.f));
            A2[2] = packh2(fmaxf(C1[2 * s + 1][0], 0.f), fmaxf(C1[2 * s + 1][1], 0.f));
            A2[3] = packh2(fmaxf(C1[2 * s + 1][2], 0.f), fmaxf(C1[2 * s + 1][3], 0.f));
            mma_f16(C2[0], A2, B2[s][0]);
            mma_f16(C2[1], A2, B2[s][1]);
        }

        // ---- residual in registers, direct stores (C2 layout == x layout) ----
        if (tg < ntok) {
            float2* o0 = (float2*)(out + (long long)tg * H);
            float2* o1 = (float2*)(out + (long long)(tg + 8) * H);
            o0[q]     = make_float2(C2[0][0] + va.x, C2[0][1] + va.y);
            o0[q + 4] = make_float2(C2[1][0] + vb.x, C2[1][1] + vb.y);
            o1[q]     = make_float2(C2[0][2] + vc.x, C2[0][3] + vc.y);
            o1[q + 4] = make_float2(C2[1][2] + vd.x, C2[1][3] + vd.y);
        }
    }
}

extern "C" void kernel_launch(void* const* d_in, const int* in_sizes, int n_in,
                              void* d_out, int out_size) {
    const float* x     = (const float*)d_in[0];
    const float* gamma = (const float*)d_in[1];
    const float* beta  = (const float*)d_in[2];
    const float* w1    = (const float*)d_in[3];
    const float* b1    = (const float*)d_in[4];
    const float* w2    = (const float*)d_in[5];
    const float* b2    = (const float*)d_in[6];
    float* out         = (float*)d_out;

    const int ntok = in_sizes[0] / H;   // 1,048,576 (multiple of 16)
    const int threads = 128;            // 4 warps x 16 tokens
    int blocks = 148 * 4;               // persistent grid-stride
    ffn_mma<<<blocks, threads>>>(x, gamma, beta, w1, b1, w2, b2, out, ntok);
}

// round 8
// speedup vs baseline: 1.0034x; 1.0034x over previous
#include <cuda_runtime.h>
#include <cstdint>

// FFN_36867999269234 via mma.sync m16n8k16.f16 (f32 accum), zero-smem mainloop,
// software-pipelined:
//   stage i:   MMA1(i) -> [LN(i+1) overlapped] -> relu/cvt -> MMA2(i) -> STG(i)
//   prefetch:  x(i+2) LDGs issued at iteration top (distance-2)
// Fragment-layout ownership (lane g=lane>>2, q=lane&3 owns x[g][2q..],
// x[g][2q+8..], x[g+8][...]) makes LDG/LN/cvt/STG all register-local.

#define H 16
#define DM 64
#define LN_EPS 1e-5f

__device__ __forceinline__ uint32_t packh2(float lo, float hi) {
    uint32_t r;
    asm("cvt.rn.f16x2.f32 %0, %1, %2;" : "=r"(r) : "f"(hi), "f"(lo));
    return r;
}

__device__ __forceinline__ void mma_f16(float* c, const uint32_t* a, const uint32_t* b) {
    asm volatile(
        "mma.sync.aligned.m16n8k16.row.col.f32.f16.f16.f32 "
        "{%0,%1,%2,%3}, {%4,%5,%6,%7}, {%8,%9}, {%0,%1,%2,%3};"
        : "+f"(c[0]), "+f"(c[1]), "+f"(c[2]), "+f"(c[3])
        : "r"(a[0]), "r"(a[1]), "r"(a[2]), "r"(a[3]), "r"(b[0]), "r"(b[1]));
}

// LN + A1-fragment build from an x-fragment (a,b = row g cols 2q/2q+8; c,d = row g+8)
__device__ __forceinline__ void ln_to_frag(const float2 a, const float2 b,
                                           const float2 c, const float2 d,
                                           uint32_t* A) {
    float s0 = a.x + a.y + b.x + b.y;
    float s1 = c.x + c.y + d.x + d.y;
    float q0 = fmaf(a.x, a.x, a.y * a.y) + fmaf(b.x, b.x, b.y * b.y);
    float q1 = fmaf(c.x, c.x, c.y * c.y) + fmaf(d.x, d.x, d.y * d.y);
    s0 += __shfl_xor_sync(0xFFFFFFFFu, s0, 1);
    s1 += __shfl_xor_sync(0xFFFFFFFFu, s1, 1);
    q0 += __shfl_xor_sync(0xFFFFFFFFu, q0, 1);
    q1 += __shfl_xor_sync(0xFFFFFFFFu, q1, 1);
    s0 += __shfl_xor_sync(0xFFFFFFFFu, s0, 2);
    s1 += __shfl_xor_sync(0xFFFFFFFFu, s1, 2);
    q0 += __shfl_xor_sync(0xFFFFFFFFu, q0, 2);
    q1 += __shfl_xor_sync(0xFFFFFFFFu, q1, 2);
    const float m0 = s0 * (1.f / H);
    const float m1 = s1 * (1.f / H);
    const float r0 = rsqrtf(q0 * (1.f / H) - m0 * m0 + LN_EPS);
    const float r1 = rsqrtf(q1 * (1.f / H) - m1 * m1 + LN_EPS);
    A[0] = packh2((a.x - m0) * r0, (a.y - m0) * r0);
    A[1] = packh2((c.x - m1) * r1, (c.y - m1) * r1);
    A[2] = packh2((b.x - m0) * r0, (b.y - m0) * r0);
    A[3] = packh2((d.x - m1) * r1, (d.y - m1) * r1);
}

__global__ __launch_bounds__(128, 4) void ffn_mma(
    const float* __restrict__ x,
    const float* __restrict__ gamma,
    const float* __restrict__ beta,
    const float* __restrict__ w1,   // [DM, H]
    const float* __restrict__ b1,   // [DM]
    const float* __restrict__ w2,   // [H, DM]
    const float* __restrict__ b2,   // [H]
    float* __restrict__ out,
    int ntok)
{
    __shared__ float2 c1bs[8][4];   // folded b1, [ntile j][q] = cols 2q,2q+1
    __shared__ float2 c2bs[2][4];   // b2

    const int tid  = threadIdx.x;
    const int wid  = tid >> 5;
    const int lane = tid & 31;
    const int g = lane >> 2;
    const int q = lane & 3;

    // ---------------- weight fragments (f16x2, registers) ----------------
    uint32_t B1[8][2];
    #pragma unroll
    for (int j = 0; j < 8; j++) {
        const float* wr = w1 + (8 * j + g) * H;
        B1[j][0] = packh2(wr[2 * q]     * gamma[2 * q],     wr[2 * q + 1] * gamma[2 * q + 1]);
        B1[j][1] = packh2(wr[2 * q + 8] * gamma[2 * q + 8], wr[2 * q + 9] * gamma[2 * q + 9]);
    }
    uint32_t B2[4][2][2];
    #pragma unroll
    for (int s = 0; s < 4; s++)
        #pragma unroll
        for (int jn = 0; jn < 2; jn++) {
            const float* wr = w2 + (8 * jn + g) * DM + 16 * s;
            B2[s][jn][0] = packh2(wr[2 * q],     wr[2 * q + 1]);
            B2[s][jn][1] = packh2(wr[2 * q + 8], wr[2 * q + 9]);
        }

    // ---------------- bias LUTs (smem, loop-invariant) ----------------
    if (tid < 32) {
        int j = tid >> 2, qq = tid & 3;
        float a0 = b1[8 * j + 2 * qq], a1 = b1[8 * j + 2 * qq + 1];
        #pragma unroll
        for (int k = 0; k < H; k++) {
            a0 = fmaf(w1[(8 * j + 2 * qq) * H + k],     beta[k], a0);
            a1 = fmaf(w1[(8 * j + 2 * qq + 1) * H + k], beta[k], a1);
        }
        c1bs[j][qq] = make_float2(a0, a1);
    }
    if (tid < 8) {
        int jn = tid >> 2, qq = tid & 3;
        c2bs[jn][qq] = make_float2(b2[8 * jn + 2 * qq], b2[8 * jn + 2 * qq + 1]);
    }
    __syncthreads();

    // ---------------- pipelined token loop: 16 tokens/warp-tile ----------------
    const int ntiles = ntok >> 4;             // ntok multiple of 16
    const int wstep  = gridDim.x * 4;
    const int wt0    = blockIdx.x * 4 + wid;
    if (wt0 >= ntiles) return;

    // lane-fragment base offsets (elements)
    const long long e0 = (long long)g * H + 2 * q;          // row g,  cols 2q
    const long long e1 = e0 + 8;                            // row g,  cols 2q+8
    const long long e2 = (long long)(g + 8) * H + 2 * q;    // row g+8
    const long long e3 = e2 + 8;

    auto loadfrag = [&](int wt, float2& a, float2& b, float2& c, float2& d) {
        const float* p = x + ((long long)wt << 4) * H;
        a = *(const float2*)(p + e0);
        b = *(const float2*)(p + e1);
        c = *(const float2*)(p + e2);
        d = *(const float2*)(p + e3);
    };

    // preamble: tiles wt0 (v*) and wt0+1 (n*)
    float2 va, vb, vc, vd, na, nb, nc, nd;
    loadfrag(wt0, va, vb, vc, vd);
    {
        int w1t = wt0 + wstep < ntiles ? wt0 + wstep : wt0;
        loadfrag(w1t, na, nb, nc, nd);
    }
    uint32_t A1[4];
    ln_to_frag(va, vb, vc, vd, A1);

    for (int wt = wt0; wt < ntiles; wt += wstep) {
        // ---- prefetch x(i+2) ----
        float2 pa, pb, pc, pd;
        {
            int w2t = wt + 2 * wstep;
            if (w2t >= ntiles) w2t = wt;
            loadfrag(w2t, pa, pb, pc, pd);
        }

        // ---- MMA1(i): C1[16x64] = y·W1g^T + b1fold ----
        float C1[8][4];
        #pragma unroll
        for (int j = 0; j < 8; j++) {
            const float2 b = c1bs[j][q];
            C1[j][0] = b.x; C1[j][1] = b.y; C1[j][2] = b.x; C1[j][3] = b.y;
            mma_f16(C1[j], A1, B1[j]);
        }

        // ---- LN(i+1) overlapped with MMA1 latency ----
        uint32_t A1n[4];
        ln_to_frag(na, nb, nc, nd, A1n);

        // ---- MMA2(i): C2 = relu(C1)·W2^T + b2 (C->A frag identity) ----
        float C2[2][4];
        #pragma unroll
        for (int jn = 0; jn < 2; jn++) {
            const float2 b = c2bs[jn][q];
            C2[jn][0] = b.x; C2[jn][1] = b.y; C2[jn][2] = b.x; C2[jn][3] = b.y;
        }
        #pragma unroll
        for (int s = 0; s < 4; s++) {
            uint32_t A2[4];
            A2[0] = packh2(fmaxf(C1[2 * s][0], 0.f),     fmaxf(C1[2 * s][1], 0.f));
            A2[1] = packh2(fmaxf(C1[2 * s][2], 0.f),     fmaxf(C1[2 * s][3], 0.f));
            A2[2] = packh2(fmaxf(C1[2 * s + 1][0], 0.f), fmaxf(C1[2 * s + 1][1], 0.f));
            A2[3] = packh2(fmaxf(C1[2 * s + 1][2], 0.f), fmaxf(C1[2 * s + 1][3], 0.f));
            mma_f16(C2[0], A2, B2[s][0]);
            mma_f16(C2[1], A2, B2[s][1]);
        }

        // ---- residual in registers, direct stores ----
        {
            float* p = out + ((long long)wt << 4) * H;
            *(float2*)(p + e0) = make_float2(C2[0][0] + va.x, C2[0][1] + va.y);
            *(float2*)(p + e1) = make_float2(C2[1][0] + vb.x, C2[1][1] + vb.y);
            *(float2*)(p + e2) = make_float2(C2[0][2] + vc.x, C2[0][3] + vc.y);
            *(float2*)(p + e3) = make_float2(C2[1][2] + vd.x, C2[1][3] + vd.y);
        }

        // ---- rotate pipeline state ----
        va = na; vb = nb; vc = nc; vd = nd;
        na = pa; nb = pb; nc = pc; nd = pd;
        A1[0] = A1n[0]; A1[1] = A1n[1]; A1[2] = A1n[2]; A1[3] = A1n[3];
    }
}

extern "C" void kernel_launch(void* const* d_in, const int* in_sizes, int n_in,
                              void* d_out, int out_size) {
    const float* x     = (const float*)d_in[0];
    const float* gamma = (const float*)d_in[1];
    const float* beta  = (const float*)d_in[2];
    const float* w1    = (const float*)d_in[3];
    const float* b1    = (const float*)d_in[4];
    const float* w2    = (const float*)d_in[5];
    const float* b2    = (const float*)d_in[6];
    float* out         = (float*)d_out;

    const int ntok = in_sizes[0] / H;   // 1,048,576 (multiple of 16)
    const int threads = 128;            // 4 warps x 16 tokens
    int blocks = 148 * 4;               // persistent grid-stride
    ffn_mma<<<blocks, threads>>>(x, gamma, beta, w1, b1, w2, b2, out, ntok);
}